// round 1
// baseline (speedup 1.0000x reference)
#include <cuda_runtime.h>
#include <math.h>

// Problem constants
#define L_SEQ 4096
#define C_DIM 768
#define NH    12
#define HD    64
#define N_QKV 2304            // 3*C
#define ATT_SCALE 0.125f      // 64^-0.5

// Scratch (allocation-free rule: __device__ globals)
__device__ float g_qkv[L_SEQ * N_QKV];   // [l][3C] : q at 0, k at 768, v at 1536
__device__ float g_att[L_SEQ * C_DIM];   // [l][h*64+d]

// ---------------------------------------------------------------------------
// SGEMM: C[M,N] = A[M,K] * B[K,N] (+bias), row-major everywhere.
// 128x128 block tile, K-step 8, 256 threads, 8x8 per thread.
// Requires M%128==0, N%128==0, K%8==0 (true for all three uses).
// ---------------------------------------------------------------------------
template<bool BIAS>
__global__ __launch_bounds__(256) void sgemm_kernel(
    const float* __restrict__ A, const float* __restrict__ B,
    const float* __restrict__ bias, float* __restrict__ Cmat,
    int M, int N, int K)
{
    __shared__ __align__(16) float As[8][128];   // A^T tile: As[k][m]
    __shared__ __align__(16) float Bs[8][128];   // Bs[k][n]

    const int tid = threadIdx.x;
    const int m0 = blockIdx.y * 128;
    const int n0 = blockIdx.x * 128;

    const int ar = tid >> 1;          // 0..127 (A row in tile)
    const int ak = (tid & 1) * 4;     // 0 or 4 (A k offset)
    const int br = tid >> 5;          // 0..7   (B k row)
    const int bn = (tid & 31) * 4;    // 0..124 (B n offset)

    const int tx = tid & 15;
    const int ty = tid >> 4;

    float acc[8][8];
#pragma unroll
    for (int i = 0; i < 8; i++)
#pragma unroll
        for (int j = 0; j < 8; j++) acc[i][j] = 0.f;

    for (int k0 = 0; k0 < K; k0 += 8) {
        float4 a4 = *(const float4*)&A[(size_t)(m0 + ar) * K + k0 + ak];
        float4 b4 = *(const float4*)&B[(size_t)(k0 + br) * N + n0 + bn];
        __syncthreads();   // previous compute done before overwrite
        As[ak + 0][ar] = a4.x;
        As[ak + 1][ar] = a4.y;
        As[ak + 2][ar] = a4.z;
        As[ak + 3][ar] = a4.w;
        *(float4*)&Bs[br][bn] = b4;
        __syncthreads();
#pragma unroll
        for (int kk = 0; kk < 8; kk++) {
            float4 a0 = *(const float4*)&As[kk][ty * 8];
            float4 a1 = *(const float4*)&As[kk][ty * 8 + 4];
            float4 b0 = *(const float4*)&Bs[kk][tx * 8];
            float4 b1 = *(const float4*)&Bs[kk][tx * 8 + 4];
            float ra[8] = {a0.x, a0.y, a0.z, a0.w, a1.x, a1.y, a1.z, a1.w};
            float rb[8] = {b0.x, b0.y, b0.z, b0.w, b1.x, b1.y, b1.z, b1.w};
#pragma unroll
            for (int i = 0; i < 8; i++)
#pragma unroll
                for (int j = 0; j < 8; j++)
                    acc[i][j] += ra[i] * rb[j];
        }
    }

#pragma unroll
    for (int i = 0; i < 8; i++) {
        const int m = m0 + ty * 8 + i;
#pragma unroll
        for (int j = 0; j < 8; j++) {
            const int n = n0 + tx * 8 + j;
            float v = acc[i][j];
            if (BIAS) v += bias[n];
            Cmat[(size_t)m * N + n] = v;
        }
    }
}

// ---------------------------------------------------------------------------
// Fused flash-attention (fp32, online softmax).
// Grid: (L/64, H). Block: 256 threads (16x16), 4x4 micro-tile over 64x64.
// Dynamic smem: Qs/Ks/Vs/Ps each [64][65] floats = 66560 B total.
// ---------------------------------------------------------------------------
#define BM 64
#define BN 64
#define PAD 65
#define ATTN_SMEM (4 * 64 * PAD * 4)

__global__ __launch_bounds__(256) void attn_kernel(const float* __restrict__ qkv,
                                                   float* __restrict__ att)
{
    extern __shared__ float sm[];
    float* Qs = sm;                  // [64][PAD], pre-scaled by ATT_SCALE
    float* Ks = sm + 64 * PAD;       // [64][PAD]
    float* Vs = sm + 2 * 64 * PAD;   // [64][PAD]
    float* Ps = sm + 3 * 64 * PAD;   // [64][PAD]

    const int tid = threadIdx.x;
    const int h = blockIdx.y;
    const int m0 = blockIdx.x * BM;
    const int tx = tid & 15;
    const int ty = tid >> 4;
    const int hoff = h * HD;

    // Load Q tile (64 rows x 64 d), pre-scaled
#pragma unroll
    for (int rep = 0; rep < 4; rep++) {
        int idx = tid + rep * 256;        // 0..1023
        int r = idx >> 4;                 // 0..63
        int d = (idx & 15) << 2;          // 0..60
        float4 v = *(const float4*)&qkv[(size_t)(m0 + r) * N_QKV + hoff + d];
        Qs[r * PAD + d + 0] = v.x * ATT_SCALE;
        Qs[r * PAD + d + 1] = v.y * ATT_SCALE;
        Qs[r * PAD + d + 2] = v.z * ATT_SCALE;
        Qs[r * PAD + d + 3] = v.w * ATT_SCALE;
    }

    float m_i[4], l_i[4], o[4][4];
#pragma unroll
    for (int i = 0; i < 4; i++) {
        m_i[i] = -INFINITY;
        l_i[i] = 0.f;
#pragma unroll
        for (int c = 0; c < 4; c++) o[i][c] = 0.f;
    }

    for (int kb = 0; kb < L_SEQ / BN; kb++) {
        const int kr0 = kb * BN;

        // Prefetch K/V tiles into registers (overlaps with the barrier)
        float4 kv[4], vv[4];
#pragma unroll
        for (int rep = 0; rep < 4; rep++) {
            int idx = tid + rep * 256;
            int r = idx >> 4;
            int d = (idx & 15) << 2;
            kv[rep] = *(const float4*)&qkv[(size_t)(kr0 + r) * N_QKV + C_DIM + hoff + d];
            vv[rep] = *(const float4*)&qkv[(size_t)(kr0 + r) * N_QKV + 2 * C_DIM + hoff + d];
        }
        __syncthreads();   // previous iteration done reading Ks/Vs/Ps
#pragma unroll
        for (int rep = 0; rep < 4; rep++) {
            int idx = tid + rep * 256;
            int r = idx >> 4;
            int d = (idx & 15) << 2;
            Ks[r * PAD + d + 0] = kv[rep].x;
            Ks[r * PAD + d + 1] = kv[rep].y;
            Ks[r * PAD + d + 2] = kv[rep].z;
            Ks[r * PAD + d + 3] = kv[rep].w;
            Vs[r * PAD + d + 0] = vv[rep].x;
            Vs[r * PAD + d + 1] = vv[rep].y;
            Vs[r * PAD + d + 2] = vv[rep].z;
            Vs[r * PAD + d + 3] = vv[rep].w;
        }
        __syncthreads();

        // GEMM1: S = (Q*scale) @ K^T, 4x4 micro-tile
        float s[4][4];
#pragma unroll
        for (int i = 0; i < 4; i++)
#pragma unroll
            for (int j = 0; j < 4; j++) s[i][j] = 0.f;

#pragma unroll 16
        for (int d = 0; d < 64; d++) {
            float qa[4], kr[4];
#pragma unroll
            for (int i = 0; i < 4; i++) qa[i] = Qs[(ty * 4 + i) * PAD + d];
#pragma unroll
            for (int j = 0; j < 4; j++) kr[j] = Ks[(tx * 4 + j) * PAD + d];
#pragma unroll
            for (int i = 0; i < 4; i++)
#pragma unroll
                for (int j = 0; j < 4; j++)
                    s[i][j] += qa[i] * kr[j];
        }

        // Online softmax update (per row; 16 lanes share each row)
#pragma unroll
        for (int i = 0; i < 4; i++) {
            float rm = fmaxf(fmaxf(s[i][0], s[i][1]), fmaxf(s[i][2], s[i][3]));
            rm = fmaxf(rm, __shfl_xor_sync(0xffffffffu, rm, 1));
            rm = fmaxf(rm, __shfl_xor_sync(0xffffffffu, rm, 2));
            rm = fmaxf(rm, __shfl_xor_sync(0xffffffffu, rm, 4));
            rm = fmaxf(rm, __shfl_xor_sync(0xffffffffu, rm, 8));
            float mn = fmaxf(m_i[i], rm);
            float corr = __expf(m_i[i] - mn);
            m_i[i] = mn;
            float rs = 0.f;
#pragma unroll
            for (int j = 0; j < 4; j++) {
                s[i][j] = __expf(s[i][j] - mn);
                rs += s[i][j];
            }
            rs += __shfl_xor_sync(0xffffffffu, rs, 1);
            rs += __shfl_xor_sync(0xffffffffu, rs, 2);
            rs += __shfl_xor_sync(0xffffffffu, rs, 4);
            rs += __shfl_xor_sync(0xffffffffu, rs, 8);
            l_i[i] = l_i[i] * corr + rs;
#pragma unroll
            for (int c = 0; c < 4; c++) o[i][c] *= corr;
#pragma unroll
            for (int j = 0; j < 4; j++)
                Ps[(ty * 4 + i) * PAD + tx * 4 + j] = s[i][j];
        }
        __syncthreads();   // Ps visible to all

        // GEMM2: O += P @ V
#pragma unroll 16
        for (int j = 0; j < 64; j++) {
            float pa[4], vb[4];
#pragma unroll
            for (int i = 0; i < 4; i++) pa[i] = Ps[(ty * 4 + i) * PAD + j];
#pragma unroll
            for (int c = 0; c < 4; c++) vb[c] = Vs[j * PAD + tx * 4 + c];
#pragma unroll
            for (int i = 0; i < 4; i++)
#pragma unroll
                for (int c = 0; c < 4; c++)
                    o[i][c] += pa[i] * vb[c];
        }
    }

    // Epilogue: normalize and scatter to [l][h*64+d]
#pragma unroll
    for (int i = 0; i < 4; i++) {
        float inv = 1.f / l_i[i];
#pragma unroll
        for (int c = 0; c < 4; c++) {
            att[(size_t)(m0 + ty * 4 + i) * C_DIM + hoff + tx * 4 + c] = o[i][c] * inv;
        }
    }
}

// ---------------------------------------------------------------------------
extern "C" void kernel_launch(void* const* d_in, const int* in_sizes, int n_in,
                              void* d_out, int out_size)
{
    const float* x      = (const float*)d_in[0];   // [4096, 768]
    const float* w_qkv  = (const float*)d_in[1];   // [768, 2304]
    const float* w_proj = (const float*)d_in[2];   // [768, 768]
    const float* b_proj = (const float*)d_in[3];   // [768]
    float* out = (float*)d_out;                    // [4096, 768]

    float *qkv_p = nullptr, *att_p = nullptr;
    cudaGetSymbolAddress((void**)&qkv_p, g_qkv);
    cudaGetSymbolAddress((void**)&att_p, g_att);

    cudaFuncSetAttribute(attn_kernel,
                         cudaFuncAttributeMaxDynamicSharedMemorySize, ATTN_SMEM);

    // 1) QKV projection
    dim3 g1(N_QKV / 128, L_SEQ / 128);
    sgemm_kernel<false><<<g1, 256>>>(x, w_qkv, nullptr, qkv_p,
                                     L_SEQ, N_QKV, C_DIM);

    // 2) Fused attention
    dim3 g2(L_SEQ / BM, NH);
    attn_kernel<<<g2, 256, ATTN_SMEM>>>(qkv_p, att_p);

    // 3) Output projection + bias
    dim3 g3(C_DIM / 128, L_SEQ / 128);
    sgemm_kernel<true><<<g3, 256>>>(att_p, w_proj, b_proj, out,
                                    L_SEQ, C_DIM, C_DIM);
}